// round 6
// baseline (speedup 1.0000x reference)
#include <cuda_runtime.h>
#include <cuda_fp16.h>

// SpatialTransformer: 3D trilinear warp, dense displacement field.
// vol: [B=2, D=160, H=160, W=160, C=2] f32, trf: [B,D,H,W,3] f32 -> out like vol.
//
// Scheme:
//  - E2[b][y][x][z] (z-INNERMOST): 2x2 (y,x)-corner block in fp16 (clip baked
//    in), one uint4 (16B) per entry; the two z-planes a voxel needs are
//    contiguous (same 128B line 7/8 of the time).
//  - Main: 2 lanes per voxel (even lane -> z0 plane, odd -> z1), one 16B
//    gather per lane; 4 voxels per lane for MLP; planes combined via shfl_xor.
//    trf reads use __ldcs and out stores __stcs (evict-first) so the L2 keeps
//    E2 lines instead of streaming data.
//  - Prologue: float4-load / float2-smem transpose, 512-thread blocks.
// Reference semantics preserved exactly:
//   l0c = clip(floor(loc),0,159); l1c = clip(l0c+1,0,159)
//   d1  = l1c - loc (floor weight, UNCLIPPED loc); d0 = 1 - d1

#define DIM   160
#define BD    320                // B * D
#define NVOX  (BD * DIM * DIM)   // 8,192,000
#define TZ    16                 // z-tile in prologue
#define ZS2   323                // smem z-stride in float2 units (2*160 + 3 pad)
#define PTH   512                // prologue threads

// 131 MB scratch: corner-block volume, z-innermost (device global, no runtime alloc)
__device__ uint4 g_E2[NVOX];

static __device__ __forceinline__ unsigned pack_h2(float a, float b) {
    __half2 h = __floats2half2_rn(a, b);
    return *reinterpret_cast<unsigned*>(&h);
}
static __device__ __forceinline__ unsigned pack_f2(float2 v) {
    return pack_h2(v.x, v.y);
}
static __device__ __forceinline__ float2 h2f(unsigned u) {
    __half2 h = *reinterpret_cast<__half2*>(&u);
    return __half22float2(h);
}

// ---------------------------------------------------------------------------
// Prologue: build E2 (z-innermost) via smem transpose.
// grid = (320 (b*DIM+y), 10 (z-tiles)), block = 512.
// ---------------------------------------------------------------------------
__global__ __launch_bounds__(PTH)
void build_E2_kernel(const float* __restrict__ vol)
{
    __shared__ float2 sm2[TZ * ZS2];   // 16*323*8 = 41.3 KB

    const int by = blockIdx.x;              // b*DIM + y
    const int b  = (by >= DIM) ? 1 : 0;
    const int y  = by - b * DIM;
    const int z0 = blockIdx.y * TZ;
    const int t  = threadIdx.x;
    const int yp = min(y + 1, DIM - 1);
    const float4* __restrict__ v4 = (const float4*)vol;

    // Load TZ z-planes x 2 y-rows x 160 x as float4 (2 voxels each), coalesced.
    // j: x4 = j%80, rr = (j/80)&1, zz = j/160   (5 iterations of 512)
    #pragma unroll
    for (int i = 0; i < (TZ * 2 * 80) / PTH; i++) {
        const int j  = i * PTH + t;
        const int x4 = j % 80;
        const int rr = (j / 80) & 1;
        const int zz = j / 160;
        const int yy = rr ? yp : y;
        const float4 v = v4[((b * DIM + z0 + zz) * DIM + yy) * 80 + x4];
        float2* s = &sm2[zz * ZS2 + rr * DIM + x4 * 2];
        s[0] = make_float2(v.x, v.y);
        s[1] = make_float2(v.z, v.w);
    }
    __syncthreads();

    // Emit entries; k: zz = k&15, x = k>>4 -> E2 writes in 256B runs.
    #pragma unroll
    for (int i = 0; i < (TZ * DIM) / PTH; i++) {
        const int k  = i * PTH + t;
        const int zz = k & (TZ - 1);
        const int x  = k >> 4;
        const int xp = min(x + 1, DIM - 1);
        const float2* s0 = &sm2[zz * ZS2];
        uint4 e;
        e.x = pack_f2(s0[x]);            // (y  , x  )
        e.y = pack_f2(s0[xp]);           // (y  , x+1)
        e.z = pack_f2(s0[DIM + x]);      // (y+1, x  )
        e.w = pack_f2(s0[DIM + xp]);     // (y+1, x+1)
        g_E2[(by * DIM + x) * DIM + (z0 + zz)] = e;
    }
}

// ---------------------------------------------------------------------------
// Main: 2 lanes per voxel (lane parity = z-plane), 4 voxels per lane.
// grid = (320 (b*D+z), 40), block = 320 (160 x-pairs); y = blockIdx.y*4 + q.
// ---------------------------------------------------------------------------
__global__ __launch_bounds__(2 * DIM)
void st_warp_kernel(const float* __restrict__ trf,
                    float* __restrict__ out)
{
    const int tid = threadIdx.x;
    const int s   = tid & 1;          // 0 -> z0 plane, 1 -> z1 plane
    const int x   = tid >> 1;         // 0..159
    const int yb  = blockIdx.y << 2;  // base y (0,4,...,156)
    const int zb  = blockIdx.x;       // 0..319 = b*D + z
    const int z   = (zb >= DIM) ? (zb - DIM) : zb;
    const int b   = (zb >= DIM) ? 1 : 0;
    const float maxl = (float)(DIM - 1);
    const float fz = (float)z;
    const float fx = (float)x;

    int   vox[4];
    float tz[4], ty[4], tx[4];
    #pragma unroll
    for (int q = 0; q < 4; q++) {
        vox[q] = (zb * DIM + (yb + q)) * DIM + x;
        // streaming loads: evict-first, keep L2 for E2 gathers
        tz[q] = __ldcs(&trf[vox[q] * 3 + 0]);
        ty[q] = __ldcs(&trf[vox[q] * 3 + 1]);
        tx[q] = __ldcs(&trf[vox[q] * 3 + 2]);
    }

    float wy0[4], wy1[4], wx0[4], wx1[4], wzs[4];
    int   idx[4];
    #pragma unroll
    for (int q = 0; q < 4; q++) {
        const float lz = fz + tz[q];
        const float ly = (float)(yb + q) + ty[q];
        const float lx = fx + tx[q];
        const float z0f = fminf(fmaxf(floorf(lz), 0.0f), maxl);
        const float y0f = fminf(fmaxf(floorf(ly), 0.0f), maxl);
        const float x0f = fminf(fmaxf(floorf(lx), 0.0f), maxl);
        const float z1f = fminf(z0f + 1.0f, maxl);
        const float y1f = fminf(y0f + 1.0f, maxl);
        const float x1f = fminf(x0f + 1.0f, maxl);
        wy0[q] = y1f - ly;  wy1[q] = 1.0f - wy0[q];
        wx0[q] = x1f - lx;  wx1[q] = 1.0f - wx0[q];
        const float wz0 = z1f - lz;
        wzs[q] = s ? (1.0f - wz0) : wz0;
        const int zs = s ? (int)z1f : (int)z0f;
        idx[q] = ((b * DIM + (int)y0f) * DIM + (int)x0f) * DIM + zs;
    }

    // 4 independent gathers in flight; lane-pair accesses share a line ~7/8.
    uint4 e[4];
    #pragma unroll
    for (int q = 0; q < 4; q++) e[q] = g_E2[idx[q]];

    #pragma unroll
    for (int q = 0; q < 4; q++) {
        const float w00 = wy0[q] * wx0[q], w01 = wy0[q] * wx1[q];
        const float w10 = wy1[q] * wx0[q], w11 = wy1[q] * wx1[q];
        const float2 c00 = h2f(e[q].x), c01 = h2f(e[q].y);
        const float2 c10 = h2f(e[q].z), c11 = h2f(e[q].w);
        float p0 = w00 * c00.x, p1 = w00 * c00.y;
        p0 = fmaf(w01, c01.x, p0);  p1 = fmaf(w01, c01.y, p1);
        p0 = fmaf(w10, c10.x, p0);  p1 = fmaf(w10, c10.y, p1);
        p0 = fmaf(w11, c11.x, p0);  p1 = fmaf(w11, c11.y, p1);
        float r0 = wzs[q] * p0;
        float r1 = wzs[q] * p1;
        // combine the two z-planes across the lane pair
        r0 += __shfl_xor_sync(0xffffffffu, r0, 1);
        r1 += __shfl_xor_sync(0xffffffffu, r1, 1);
        // lane s stores channel s -> streaming store, evict-first
        __stcs(&out[vox[q] * 2 + s], s ? r1 : r0);
    }
}

extern "C" void kernel_launch(void* const* d_in, const int* in_sizes, int n_in,
                              void* d_out, int out_size)
{
    const float* vol = (const float*)d_in[0];
    const float* trf = (const float*)d_in[1];
    float* out = (float*)d_out;

    dim3 pgrid(BD, DIM / TZ, 1);      // (b*DIM + y, z-tile)
    build_E2_kernel<<<pgrid, PTH>>>(vol);

    dim3 mgrid(BD, DIM / 4, 1);       // (b*D + z, y/4)
    st_warp_kernel<<<mgrid, 2 * DIM>>>(trf, out);
}

// round 8
// speedup vs baseline: 1.0226x; 1.0226x over previous
#include <cuda_runtime.h>
#include <cuda_fp16.h>

// SpatialTransformer: 3D trilinear warp, dense displacement field.
// vol: [B=2, D=160, H=160, W=160, C=2] f32, trf: [B,D,H,W,3] f32 -> out like vol.
//
// Scheme:
//  - E2[b][y][x][z] (z-INNERMOST): 2x2 (y,x)-corner block in fp16 (clip baked
//    in), one uint4 (16B) per entry; the two z-planes a voxel needs are
//    contiguous (same 128B line 7/8 of the time).
//  - Main: 2 lanes per voxel (even lane -> z0 plane, odd -> z1), one 16B
//    gather per lane; 4 voxels per lane; planes combined via ONE shfl_xor/q.
//    Gather indices via exact f32 FMA chain (values < 2^23).
//  - Prologue: float4-load / float2-smem transpose (R5 version, 256 thr).
// Reference semantics preserved exactly:
//   l0c = clip(floor(loc),0,159); l1c = clip(l0c+1,0,159)
//   d1  = l1c - loc (floor weight, UNCLIPPED loc); d0 = 1 - d1

#define DIM   160
#define BD    320                // B * D
#define NVOX  (BD * DIM * DIM)   // 8,192,000
#define TZ    16                 // z-tile in prologue
#define ZS2   323                // smem z-stride in float2 units (2*160 + 3 pad)

// 131 MB scratch: corner-block volume, z-innermost (device global, no runtime alloc)
__device__ uint4 g_E2[NVOX];

static __device__ __forceinline__ unsigned pack_h2(float a, float b) {
    __half2 h = __floats2half2_rn(a, b);
    return *reinterpret_cast<unsigned*>(&h);
}
static __device__ __forceinline__ unsigned pack_f2(float2 v) {
    return pack_h2(v.x, v.y);
}
static __device__ __forceinline__ float2 h2f(unsigned u) {
    __half2 h = *reinterpret_cast<__half2*>(&u);
    return __half22float2(h);
}

// ---------------------------------------------------------------------------
// Prologue: build E2 (z-innermost) via smem transpose.
// grid = (320 (b*DIM+y), 10 (z-tiles)), block = 256.
// ---------------------------------------------------------------------------
__global__ __launch_bounds__(256)
void build_E2_kernel(const float* __restrict__ vol)
{
    __shared__ float2 sm2[TZ * ZS2];   // 16*323*8 = 41.3 KB

    const int by = blockIdx.x;              // b*DIM + y
    const int b  = (by >= DIM) ? 1 : 0;
    const int y  = by - b * DIM;
    const int z0 = blockIdx.y * TZ;
    const int t  = threadIdx.x;
    const int yp = min(y + 1, DIM - 1);
    const float4* __restrict__ v4 = (const float4*)vol;

    // Load TZ z-planes x 2 y-rows x 160 x as float4 (2 voxels each), coalesced.
    #pragma unroll
    for (int i = 0; i < (TZ * 2 * 80) / 256; i++) {
        const int j  = i * 256 + t;
        const int x4 = j % 80;
        const int rr = (j / 80) & 1;
        const int zz = j / 160;
        const int yy = rr ? yp : y;
        const float4 v = v4[((b * DIM + z0 + zz) * DIM + yy) * 80 + x4];
        float2* s = &sm2[zz * ZS2 + rr * DIM + x4 * 2];
        s[0] = make_float2(v.x, v.y);
        s[1] = make_float2(v.z, v.w);
    }
    __syncthreads();

    // Emit entries; k: zz = k&15, x = k>>4 -> E2 writes in 256B runs.
    #pragma unroll
    for (int i = 0; i < (TZ * DIM) / 256; i++) {
        const int k  = i * 256 + t;
        const int zz = k & (TZ - 1);
        const int x  = k >> 4;
        const int xp = min(x + 1, DIM - 1);
        const float2* s0 = &sm2[zz * ZS2];
        uint4 e;
        e.x = pack_f2(s0[x]);            // (y  , x  )
        e.y = pack_f2(s0[xp]);           // (y  , x+1)
        e.z = pack_f2(s0[DIM + x]);      // (y+1, x  )
        e.w = pack_f2(s0[DIM + xp]);     // (y+1, x+1)
        g_E2[(by * DIM + x) * DIM + (z0 + zz)] = e;
    }
}

// ---------------------------------------------------------------------------
// Main: 2 lanes per voxel (lane parity = z-plane), 4 voxels per lane.
// grid = (320 (b*D+z), 40), block = 320 (160 x-pairs); y = blockIdx.y*4 + q.
// ---------------------------------------------------------------------------
__global__ __launch_bounds__(2 * DIM)
void st_warp_kernel(const float* __restrict__ trf,
                    float* __restrict__ out)
{
    const int tid = threadIdx.x;
    const int s   = tid & 1;          // 0 -> z0 plane, 1 -> z1 plane
    const int x   = tid >> 1;         // 0..159
    const int yb  = blockIdx.y << 2;  // base y (0,4,...,156)
    const int zb  = blockIdx.x;       // 0..319 = b*D + z
    const int z   = (zb >= DIM) ? (zb - DIM) : zb;
    const float bOff = (zb >= DIM) ? 4096000.0f : 0.0f;  // b * 160^3 (exact f32)
    const float maxl = (float)(DIM - 1);
    const float fz = (float)z;
    const float fx = (float)x;

    int   vox[4];
    float tz[4], ty[4], tx[4];
    #pragma unroll
    for (int q = 0; q < 4; q++) {
        vox[q] = (zb * DIM + (yb + q)) * DIM + x;
        tz[q] = trf[vox[q] * 3 + 0];
        ty[q] = trf[vox[q] * 3 + 1];
        tx[q] = trf[vox[q] * 3 + 2];
    }

    float wy0[4], wy1[4], wx0[4], wx1[4], wzs[4];
    int   idx[4];
    #pragma unroll
    for (int q = 0; q < 4; q++) {
        const float lz = fz + tz[q];
        const float ly = (float)(yb + q) + ty[q];
        const float lx = fx + tx[q];
        const float z0f = fminf(fmaxf(floorf(lz), 0.0f), maxl);
        const float y0f = fminf(fmaxf(floorf(ly), 0.0f), maxl);
        const float x0f = fminf(fmaxf(floorf(lx), 0.0f), maxl);
        const float z1f = fminf(z0f + 1.0f, maxl);
        const float y1f = fminf(y0f + 1.0f, maxl);
        const float x1f = fminf(x0f + 1.0f, maxl);
        wy0[q] = y1f - ly;  wy1[q] = 1.0f - wy0[q];
        wx0[q] = x1f - lx;  wx1[q] = 1.0f - wx0[q];
        const float wz0 = z1f - lz;
        wzs[q] = s ? (1.0f - wz0) : wz0;
        const float zsf = s ? z1f : z0f;
        // exact integer arithmetic in f32: value < 2^23
        const float fidx = fmaf(y0f, 25600.0f, fmaf(x0f, 160.0f, zsf)) + bOff;
        idx[q] = (int)fidx;
    }

    // 4 independent gathers in flight; lane-pair accesses share a line ~7/8.
    uint4 e[4];
    #pragma unroll
    for (int q = 0; q < 4; q++) e[q] = g_E2[idx[q]];

    #pragma unroll
    for (int q = 0; q < 4; q++) {
        const float w00 = wy0[q] * wx0[q], w01 = wy0[q] * wx1[q];
        const float w10 = wy1[q] * wx0[q], w11 = wy1[q] * wx1[q];
        const float2 c00 = h2f(e[q].x), c01 = h2f(e[q].y);
        const float2 c10 = h2f(e[q].z), c11 = h2f(e[q].w);
        float p0 = w00 * c00.x, p1 = w00 * c00.y;
        p0 = fmaf(w01, c01.x, p0);  p1 = fmaf(w01, c01.y, p1);
        p0 = fmaf(w10, c10.x, p0);  p1 = fmaf(w10, c10.y, p1);
        p0 = fmaf(w11, c11.x, p0);  p1 = fmaf(w11, c11.y, p1);
        const float r0 = wzs[q] * p0;
        const float r1 = wzs[q] * p1;
        // single-shfl combine: each lane exports the channel the peer stores
        const float send = s ? r0 : r1;
        const float recv = __shfl_xor_sync(0xffffffffu, send, 1);
        // lane s stores channel s -> warp stores are contiguous 128B runs
        out[vox[q] * 2 + s] = (s ? r1 : r0) + recv;
    }
}

extern "C" void kernel_launch(void* const* d_in, const int* in_sizes, int n_in,
                              void* d_out, int out_size)
{
    const float* vol = (const float*)d_in[0];
    const float* trf = (const float*)d_in[1];
    float* out = (float*)d_out;

    dim3 pgrid(BD, DIM / TZ, 1);      // (b*DIM + y, z-tile)
    build_E2_kernel<<<pgrid, 256>>>(vol);

    dim3 mgrid(BD, DIM / 4, 1);       // (b*D + z, y/4)
    st_warp_kernel<<<mgrid, 2 * DIM>>>(trf, out);
}

// round 9
// speedup vs baseline: 1.1088x; 1.0844x over previous
#include <cuda_runtime.h>
#include <cuda_fp16.h>

// SpatialTransformer: 3D trilinear warp, dense displacement field.
// vol: [B=2, D=160, H=160, W=160, C=2] f32, trf: [B,D,H,W,3] f32 -> out like vol.
//
// R9 scheme:
//  - E[b][y][x][z] (z-INNERMOST), 8B entries: x-pair {v[y][x][z], v[y][x+1][z]}
//    with both channels fp16 (x-clip baked in). 65.5 MB intermediate.
//  - Main: 2 lanes per voxel (even lane -> z0 plane, odd -> z1), 2x 8B gathers
//    per lane (rows y0, y1); lane-pair z-adjacent entries share a 128B line.
//    4 voxels per lane for MLP; planes combined via ONE shfl_xor per voxel.
//    Gather indices via exact f32 FMA chain (values < 2^23).
//  - Prologue: float4-load / float2-smem transpose, single y-row per block.
// Reference semantics preserved exactly:
//   l0c = clip(floor(loc),0,159); l1c = clip(l0c+1,0,159)
//   d1  = l1c - loc (floor weight, UNCLIPPED loc); d0 = 1 - d1

#define DIM   160
#define BD    320                // B * D
#define NVOX  (BD * DIM * DIM)   // 8,192,000
#define TZ    16                 // z-tile in prologue
#define ZSP   163                // smem z-stride in float2 units (160 + 3 pad)

// 65.5 MB scratch: x-pair volume, z-innermost (device global, no runtime alloc)
__device__ uint2 g_E[NVOX];

static __device__ __forceinline__ unsigned pack_h2(float a, float b) {
    __half2 h = __floats2half2_rn(a, b);
    return *reinterpret_cast<unsigned*>(&h);
}
static __device__ __forceinline__ unsigned pack_f2(float2 v) {
    return pack_h2(v.x, v.y);
}
static __device__ __forceinline__ float2 h2f(unsigned u) {
    __half2 h = *reinterpret_cast<__half2*>(&u);
    return __half22float2(h);
}

// ---------------------------------------------------------------------------
// Prologue: build E (z-innermost x-pairs) via smem transpose.
// grid = (320 (b*DIM+y), 10 (z-tiles)), block = 256.
// ---------------------------------------------------------------------------
__global__ __launch_bounds__(256)
void build_E_kernel(const float* __restrict__ vol)
{
    __shared__ float2 sm2[TZ * ZSP];   // 16*163*8 = 20.9 KB

    const int by = blockIdx.x;              // b*DIM + y
    const int b  = (by >= DIM) ? 1 : 0;
    const int y  = by - b * DIM;
    const int z0 = blockIdx.y * TZ;
    const int t  = threadIdx.x;
    const float4* __restrict__ v4 = (const float4*)vol;

    // Load TZ z-planes x 160 x as float4 (2 voxels each), coalesced.
    // j: x4 = j%80, zz = j/80   (5 iterations of 256)
    #pragma unroll
    for (int i = 0; i < (TZ * 80) / 256; i++) {
        const int j  = i * 256 + t;
        const int x4 = j % 80;
        const int zz = j / 80;
        const float4 v = v4[((b * DIM + z0 + zz) * DIM + y) * 80 + x4];
        float2* s = &sm2[zz * ZSP + x4 * 2];
        s[0] = make_float2(v.x, v.y);
        s[1] = make_float2(v.z, v.w);
    }
    __syncthreads();

    // Emit entries; k: zz = k&15, x = k>>4 -> E writes in 128B runs.
    #pragma unroll
    for (int i = 0; i < (TZ * DIM) / 256; i++) {
        const int k  = i * 256 + t;
        const int zz = k & (TZ - 1);
        const int x  = k >> 4;
        const int xp = min(x + 1, DIM - 1);
        const float2* s0 = &sm2[zz * ZSP];
        uint2 e;
        e.x = pack_f2(s0[x]);            // (x  )
        e.y = pack_f2(s0[xp]);           // (x+1)
        g_E[(by * DIM + x) * DIM + (z0 + zz)] = e;
    }
}

// ---------------------------------------------------------------------------
// Main: 2 lanes per voxel (lane parity = z-plane), 4 voxels per lane,
// 2 gathers per lane per voxel (rows y0, y1).
// grid = (320 (b*D+z), 40), block = 320 (160 x-pairs); y = blockIdx.y*4 + q.
// ---------------------------------------------------------------------------
__global__ __launch_bounds__(2 * DIM)
void st_warp_kernel(const float* __restrict__ trf,
                    float* __restrict__ out)
{
    const int tid = threadIdx.x;
    const int s   = tid & 1;          // 0 -> z0 plane, 1 -> z1 plane
    const int x   = tid >> 1;         // 0..159
    const int yb  = blockIdx.y << 2;  // base y (0,4,...,156)
    const int zb  = blockIdx.x;       // 0..319 = b*D + z
    const int z   = (zb >= DIM) ? (zb - DIM) : zb;
    const float bOff = (zb >= DIM) ? 4096000.0f : 0.0f;  // b * 160^3 (exact f32)
    const float maxl = (float)(DIM - 1);
    const float fz = (float)z;
    const float fx = (float)x;

    int   vox[4];
    float tz[4], ty[4], tx[4];
    #pragma unroll
    for (int q = 0; q < 4; q++) {
        vox[q] = (zb * DIM + (yb + q)) * DIM + x;
        tz[q] = trf[vox[q] * 3 + 0];
        ty[q] = trf[vox[q] * 3 + 1];
        tx[q] = trf[vox[q] * 3 + 2];
    }

    float wy0[4], wy1[4], wx0[4], wx1[4], wzs[4];
    int   idx0[4], idx1[4];
    #pragma unroll
    for (int q = 0; q < 4; q++) {
        const float lz = fz + tz[q];
        const float ly = (float)(yb + q) + ty[q];
        const float lx = fx + tx[q];
        const float z0f = fminf(fmaxf(floorf(lz), 0.0f), maxl);
        const float y0f = fminf(fmaxf(floorf(ly), 0.0f), maxl);
        const float x0f = fminf(fmaxf(floorf(lx), 0.0f), maxl);
        const float z1f = fminf(z0f + 1.0f, maxl);
        const float y1f = fminf(y0f + 1.0f, maxl);
        const float x1f = fminf(x0f + 1.0f, maxl);
        wy0[q] = y1f - ly;  wy1[q] = 1.0f - wy0[q];
        wx0[q] = x1f - lx;  wx1[q] = 1.0f - wx0[q];
        const float wz0 = z1f - lz;
        wzs[q] = s ? (1.0f - wz0) : wz0;
        const float zsf = s ? z1f : z0f;
        // exact integer arithmetic in f32: values < 2^23
        const float inner = fmaf(x0f, 160.0f, zsf) + bOff;
        idx0[q] = (int)fmaf(y0f, 25600.0f, inner);
        idx1[q] = (int)fmaf(y1f, 25600.0f, inner);
    }

    // 8 independent gathers in flight; lane-pair accesses share a line ~7/8.
    uint2 eA[4], eB[4];
    #pragma unroll
    for (int q = 0; q < 4; q++) { eA[q] = g_E[idx0[q]]; eB[q] = g_E[idx1[q]]; }

    #pragma unroll
    for (int q = 0; q < 4; q++) {
        const float w00 = wy0[q] * wx0[q], w01 = wy0[q] * wx1[q];
        const float w10 = wy1[q] * wx0[q], w11 = wy1[q] * wx1[q];
        const float2 c00 = h2f(eA[q].x), c01 = h2f(eA[q].y);   // y0 row: x0, x1
        const float2 c10 = h2f(eB[q].x), c11 = h2f(eB[q].y);   // y1 row: x0, x1
        float p0 = w00 * c00.x, p1 = w00 * c00.y;
        p0 = fmaf(w01, c01.x, p0);  p1 = fmaf(w01, c01.y, p1);
        p0 = fmaf(w10, c10.x, p0);  p1 = fmaf(w10, c10.y, p1);
        p0 = fmaf(w11, c11.x, p0);  p1 = fmaf(w11, c11.y, p1);
        const float r0 = wzs[q] * p0;
        const float r1 = wzs[q] * p1;
        // single-shfl combine: each lane exports the channel the peer stores
        const float send = s ? r0 : r1;
        const float recv = __shfl_xor_sync(0xffffffffu, send, 1);
        // lane s stores channel s -> warp stores are contiguous 128B runs
        out[vox[q] * 2 + s] = (s ? r1 : r0) + recv;
    }
}

extern "C" void kernel_launch(void* const* d_in, const int* in_sizes, int n_in,
                              void* d_out, int out_size)
{
    const float* vol = (const float*)d_in[0];
    const float* trf = (const float*)d_in[1];
    float* out = (float*)d_out;

    dim3 pgrid(BD, DIM / TZ, 1);      // (b*DIM + y, z-tile)
    build_E_kernel<<<pgrid, 256>>>(vol);

    dim3 mgrid(BD, DIM / 4, 1);       // (b*D + z, y/4)
    st_warp_kernel<<<mgrid, 2 * DIM>>>(trf, out);
}